// round 4
// baseline (speedup 1.0000x reference)
#include <cuda_runtime.h>
#include <cuda_fp16.h>
#include <cstdint>

#define N_NODES 8192
#define D_IN    512
#define D_OUT   256
#define KC      128
#define NCH     (N_NODES / KC)
#define MT      64
#define FTHREADS 256

// ---------------- scratch (device globals) ----------------------------------
static __device__ float g_wh [N_NODES * D_OUT];            // 8 MB
static __device__ uint2 g_whB[NCH * 8 * 32 * 32];          // 4 MB, B-fragment order
static __device__ float g_ssrc[N_NODES];
static __device__ float g_sdst[N_NODES];
static __device__ float g_E[N_NODES];
static __device__ float g_F[N_NODES];

// ---------------- PTX helpers -----------------------------------------------
__device__ __forceinline__ uint32_t smem_u32(const void* p) {
    uint32_t a;
    asm("{ .reg .u64 t; cvta.to.shared.u64 t, %1; cvt.u32.u64 %0, t; }"
        : "=r"(a) : "l"(p));
    return a;
}
__device__ __forceinline__ void ldmatrix_x4(uint32_t& r0, uint32_t& r1,
                                            uint32_t& r2, uint32_t& r3,
                                            uint32_t addr) {
    asm volatile("ldmatrix.sync.aligned.m8n8.x4.shared.b16 {%0,%1,%2,%3}, [%4];"
                 : "=r"(r0), "=r"(r1), "=r"(r2), "=r"(r3) : "r"(addr));
}
__device__ __forceinline__ void mma16816(float* c,
                                         uint32_t a0, uint32_t a1, uint32_t a2, uint32_t a3,
                                         uint32_t b0, uint32_t b1) {
    asm volatile("mma.sync.aligned.m16n8k16.row.col.f32.f16.f16.f32 "
                 "{%0,%1,%2,%3}, {%4,%5,%6,%7}, {%8,%9}, {%0,%1,%2,%3};"
                 : "+f"(c[0]), "+f"(c[1]), "+f"(c[2]), "+f"(c[3])
                 : "r"(a0), "r"(a1), "r"(a2), "r"(a3), "r"(b0), "r"(b1));
}

// ==================== Kernel 1: wh = h @ W^T + b (fp32 SIMT) ================
#define BM 128
#define BN 128
#define BK 16
#define TM 8
#define TN 8

__global__ void __launch_bounds__(256) gemm_wh_kernel(
    const float* __restrict__ h, const float* __restrict__ W,
    const float* __restrict__ Wb)
{
    __shared__ float As[BK][BM + 4];
    __shared__ float Bs[BK][BN + 4];
    const int tid = threadIdx.x;
    const int tx = tid & 15;
    const int ty = tid >> 4;
    const int row0 = blockIdx.y * BM;
    const int col0 = blockIdx.x * BN;

    float acc[TM][TN];
    #pragma unroll
    for (int i = 0; i < TM; i++)
        #pragma unroll
        for (int j = 0; j < TN; j++) acc[i][j] = 0.f;

    for (int kb = 0; kb < D_IN; kb += BK) {
        #pragma unroll
        for (int l = 0; l < 2; l++) {
            int f = tid + l * 256;
            int r = f >> 2;
            int c = (f & 3) << 2;
            float4 v = *(const float4*)&h[(size_t)(row0 + r) * D_IN + kb + c];
            As[c + 0][r] = v.x; As[c + 1][r] = v.y;
            As[c + 2][r] = v.z; As[c + 3][r] = v.w;
            float4 u = *(const float4*)&W[(size_t)(col0 + r) * D_IN + kb + c];
            Bs[c + 0][r] = u.x; Bs[c + 1][r] = u.y;
            Bs[c + 2][r] = u.z; Bs[c + 3][r] = u.w;
        }
        __syncthreads();
        #pragma unroll
        for (int k = 0; k < BK; k++) {
            float a[TM], b[TN];
            #pragma unroll
            for (int i = 0; i < TM; i++) a[i] = As[k][ty * TM + i];
            #pragma unroll
            for (int j = 0; j < TN; j++) b[j] = Bs[k][tx * TN + j];
            #pragma unroll
            for (int i = 0; i < TM; i++)
                #pragma unroll
                for (int j = 0; j < TN; j++)
                    acc[i][j] += a[i] * b[j];
        }
        __syncthreads();
    }

    #pragma unroll
    for (int i = 0; i < TM; i++) {
        int gr = row0 + ty * TM + i;
        #pragma unroll
        for (int j = 0; j < TN; j += 4) {
            int gc = col0 + tx * TN + j;
            float4 v;
            v.x = acc[i][j + 0] + Wb[gc + 0];
            v.y = acc[i][j + 1] + Wb[gc + 1];
            v.z = acc[i][j + 2] + Wb[gc + 2];
            v.w = acc[i][j + 3] + Wb[gc + 3];
            *(float4*)&g_wh[(size_t)gr * D_OUT + gc] = v;
        }
    }
}

// ==================== Kernel 1b: pack wh into B-fragment order ==============
// g_whB[((kt*8+ks)*32 + nt)*32 + lane] = {b0, b1}
// b0 = half2(wh[k0][n], wh[k0+1][n]), b1 = half2(wh[k0+8][n], wh[k0+9][n])
// n = nt*8 + (lane>>2), k0 = kt*128 + ks*16 + (lane&3)*2
__global__ void __launch_bounds__(256) pack_whB_kernel()
{
    __shared__ __half t2[64][136];          // [n_local][k_local]
    const int tid = threadIdx.x;
    const int kt = blockIdx.y;              // 0..63
    const int ct = blockIdx.x;              // 0..3 (64-col tiles)
    const int j0 = kt * 128;
    const int c0 = ct * 64;

    #pragma unroll
    for (int it = 0; it < 8; it++) {
        int flat = tid + it * 256;
        int row  = flat >> 4;                // 0..127  (k_local)
        int c4   = (flat & 15) << 2;         // 0..60   (n_local base)
        float4 v = *(const float4*)&g_wh[(size_t)(j0 + row) * D_OUT + c0 + c4];
        t2[c4 + 0][row] = __float2half(v.x);
        t2[c4 + 1][row] = __float2half(v.y);
        t2[c4 + 2][row] = __float2half(v.z);
        t2[c4 + 3][row] = __float2half(v.w);
    }
    __syncthreads();

    #pragma unroll
    for (int it = 0; it < 8; it++) {
        int flat = tid + it * 256;
        int lane = flat & 31;
        int ntl  = (flat >> 5) & 7;
        int ks   = flat >> 8;
        int n_l  = ntl * 8 + (lane >> 2);
        int k_l  = ks * 16 + (lane & 3) * 2;
        uint32_t b0 = *(const uint32_t*)&t2[n_l][k_l];
        uint32_t b1 = *(const uint32_t*)&t2[n_l][k_l + 8];
        g_whB[((kt * 8 + ks) * 32 + ct * 8 + ntl) * 32 + lane] = make_uint2(b0, b1);
    }
}

// ==================== Kernel 2: per-row scores ==============================
__global__ void __launch_bounds__(256) scores_kernel(const float* __restrict__ aw)
{
    const int lane = threadIdx.x & 31;
    const int warp = threadIdx.x >> 5;
    const int row  = blockIdx.x * 8 + warp;

    const float4* whr = (const float4*)&g_wh[(size_t)row * D_OUT];
    float4 w0 = whr[lane * 2];
    float4 w1 = whr[lane * 2 + 1];
    const float4* as = (const float4*)aw;
    const float4* ad = (const float4*)(aw + D_OUT);
    float4 a0 = as[lane * 2], a1 = as[lane * 2 + 1];
    float4 b0 = ad[lane * 2], b1 = ad[lane * 2 + 1];

    float ss = w0.x*a0.x + w0.y*a0.y + w0.z*a0.z + w0.w*a0.w
             + w1.x*a1.x + w1.y*a1.y + w1.z*a1.z + w1.w*a1.w;
    float sd = w0.x*b0.x + w0.y*b0.y + w0.z*b0.z + w0.w*b0.w
             + w1.x*b1.x + w1.y*b1.y + w1.z*b1.z + w1.w*b1.w;
    #pragma unroll
    for (int o = 16; o; o >>= 1) {
        ss += __shfl_xor_sync(0xffffffffu, ss, o);
        sd += __shfl_xor_sync(0xffffffffu, sd, o);
    }
    if (lane == 0) {
        g_ssrc[row] = ss;
        g_sdst[row] = sd;
        g_E[row] = __expf(sd);
        g_F[row] = __expf(0.2f * sd);
    }
}

// ==================== Kernel 3: HMMA flash (double-buffered A, direct B) ====
#define LDA 136
static constexpr uint32_t AS_BYTES = MT * LDA * 2;         // 17408
static constexpr uint32_t TS_OFF   = 2 * AS_BYTES;         // 34816
static constexpr uint32_t LS_OFF   = TS_OFF + 3 * N_NODES * 4;   // +98304
static constexpr uint32_t SMEM_TOTAL = LS_OFF + 512;

__global__ void __launch_bounds__(FTHREADS) flash_mma_kernel(
    const int* __restrict__ adj, const float* __restrict__ abp,
    float* __restrict__ out)
{
    extern __shared__ __align__(16) char smem[];
    __half* As0 = (__half*)smem;
    float*  ts  = (float*)(smem + TS_OFF);
    float*  Es  = ts + N_NODES;
    float*  Fs  = Es + N_NODES;
    float*  lsum_s = (float*)(smem + LS_OFF);
    float*  red    = lsum_s + 64;

    const int tid  = threadIdx.x;
    const int lane = tid & 31;
    const int warp = tid >> 5;
    const int rowbase = blockIdx.x * MT;

    // ---- prestage all scalars (96 KB) ----
    {
        const float4* s4 = (const float4*)g_sdst;
        const float4* e4 = (const float4*)g_E;
        const float4* f4 = (const float4*)g_F;
        #pragma unroll
        for (int it = 0; it < 8; it++) {
            int i = tid + it * FTHREADS;
            ((float4*)ts)[i] = s4[i];
            ((float4*)Es)[i] = e4[i];
            ((float4*)Fs)[i] = f4[i];
        }
    }
    __syncthreads();

    // ---- global max of t ----
    float m = -3.0e38f;
    for (int i = tid; i < N_NODES; i += FTHREADS) m = fmaxf(m, ts[i]);
    #pragma unroll
    for (int o = 16; o; o >>= 1) m = fmaxf(m, __shfl_xor_sync(0xffffffffu, m, o));
    if (lane == 0) red[warp] = m;
    __syncthreads();
    float T = red[0];
    #pragma unroll
    for (int w = 1; w < 8; w++) T = fmaxf(T, red[w]);

    // ---- per-thread P-gen constants: prow = tid/4, pseg = tid%4 (32 j each) -
    const float ab = abp[0];
    const int prow = tid >> 2;
    const int pseg = tid & 3;
    const int row  = rowbase + prow;
    const float s  = g_ssrc[row] + ab;
    const float Mh = s + T;
    const float M  = Mh > 0.f ? Mh : 0.2f * Mh;
    const float alpha = __expf(s - M);
    const float beta  = __expf(0.2f * s - M);
    const float theta = -s;
    float lpriv = 0.f;

    const int* adjrow = adj + (size_t)row * N_NODES;
    __half* a_st = As0 + prow * LDA + pseg * 32;   // + buf*MT*LDA

    // ---- mma addressing: warp grid 2m x 4n ----
    const int mw = warp >> 2;
    const int nw = warp & 3;
    const uint32_t as_u = smem_u32(As0);
    const uint32_t a_lane0 = as_u +
        (uint32_t)(((mw * 32 + (lane & 15)) * LDA + (lane >> 4) * 8) * 2);

    float acc[2][8][4];
    #pragma unroll
    for (int mi = 0; mi < 2; mi++)
        #pragma unroll
        for (int ni = 0; ni < 8; ni++)
            #pragma unroll
            for (int u = 0; u < 4; u++) acc[mi][ni][u] = 0.f;

    // ---- P-gen for chunk kc into buffer ----
    auto pgen = [&](int kc, int buf) {
        const int k0 = kc << 7;
        const int4* ap = (const int4*)(adjrow + k0) + pseg * 8;
        __half* dst = a_st + buf * (MT * LDA);
        #pragma unroll
        for (int h2 = 0; h2 < 4; h2++) {      // 2 its per h2 -> uint4 store
            uint4 w;
            uint32_t* wp = (uint32_t*)&w;
            #pragma unroll
            for (int sub = 0; sub < 2; sub++) {
                int it = h2 * 2 + sub;
                int4 q = ap[it];
                int jb = k0 + pseg * 32 + it * 4;
                float4 t4 = *(const float4*)(ts + jb);
                float4 e4 = *(const float4*)(Es + jb);
                float4 f4 = *(const float4*)(Fs + jb);
                float p0 = q.x > 0 ? (t4.x > theta ? alpha * e4.x : beta * f4.x) : 0.f;
                float p1 = q.y > 0 ? (t4.y > theta ? alpha * e4.y : beta * f4.y) : 0.f;
                float p2 = q.z > 0 ? (t4.z > theta ? alpha * e4.z : beta * f4.z) : 0.f;
                float p3 = q.w > 0 ? (t4.w > theta ? alpha * e4.w : beta * f4.w) : 0.f;
                lpriv += (p0 + p1) + (p2 + p3);
                __half2 h0 = __floats2half2_rn(p0, p1);
                __half2 h1 = __floats2half2_rn(p2, p3);
                wp[sub * 2 + 0] = *(uint32_t*)&h0;
                wp[sub * 2 + 1] = *(uint32_t*)&h1;
            }
            *(uint4*)(dst + h2 * 8) = w;
        }
    };

    pgen(0, 0);
    __syncthreads();

    for (int kt = 0; kt < NCH; kt++) {
        const int buf = kt & 1;
        const uint32_t a_lane = a_lane0 + (uint32_t)buf * AS_BYTES;

        #pragma unroll
        for (int ks = 0; ks < 8; ks++) {
            const uint2* bp = g_whB + (((size_t)(kt * 8 + ks) * 32 + nw * 8) * 32 + lane);
            uint2 b[8];
            #pragma unroll
            for (int ni = 0; ni < 8; ni++) b[ni] = __ldg(bp + ni * 32);

            uint32_t a0[4], a1[4];
            ldmatrix_x4(a0[0], a0[1], a0[2], a0[3], a_lane + (uint32_t)(ks * 32));
            ldmatrix_x4(a1[0], a1[1], a1[2], a1[3],
                        a_lane + (uint32_t)(16 * LDA * 2 + ks * 32));
            #pragma unroll
            for (int ni = 0; ni < 8; ni++) {
                mma16816(acc[0][ni], a0[0], a0[1], a0[2], a0[3], b[ni].x, b[ni].y);
                mma16816(acc[1][ni], a1[0], a1[1], a1[2], a1[3], b[ni].x, b[ni].y);
            }
        }
        if (kt < NCH - 1) pgen(kt + 1, buf ^ 1);
        __syncthreads();
    }

    // ---- lsum: reduce over 4 threads sharing a row ----
    lpriv += __shfl_xor_sync(0xffffffffu, lpriv, 1);
    lpriv += __shfl_xor_sync(0xffffffffu, lpriv, 2);
    if ((lane & 3) == 0) lsum_s[prow] = lpriv;
    __syncthreads();

    // ---- write out ----
    #pragma unroll
    for (int mi = 0; mi < 2; mi++) {
        int r0 = mw * 32 + mi * 16 + (lane >> 2);
        int r1 = r0 + 8;
        float inv0 = 1.f / lsum_s[r0];
        float inv1 = 1.f / lsum_s[r1];
        #pragma unroll
        for (int ni = 0; ni < 8; ni++) {
            int c = nw * 64 + ni * 8 + ((lane & 3) << 1);
            float2 v0 = make_float2(acc[mi][ni][0] * inv0, acc[mi][ni][1] * inv0);
            float2 v1 = make_float2(acc[mi][ni][2] * inv1, acc[mi][ni][3] * inv1);
            *(float2*)&out[(size_t)(rowbase + r0) * D_OUT + c] = v0;
            *(float2*)&out[(size_t)(rowbase + r1) * D_OUT + c] = v1;
        }
    }
}

// ==================== launch ================================================
extern "C" void kernel_launch(void* const* d_in, const int* in_sizes, int n_in,
                              void* d_out, int out_size)
{
    const float* h   = (const float*)d_in[0];
    const int*   adj = (const int*)  d_in[1];
    const float* Ww  = (const float*)d_in[2];
    const float* Wb  = (const float*)d_in[3];
    const float* aw  = (const float*)d_in[4];
    const float* ab  = (const float*)d_in[5];
    float* out = (float*)d_out;

    cudaFuncSetAttribute(flash_mma_kernel,
                         cudaFuncAttributeMaxDynamicSharedMemorySize, SMEM_TOTAL);

    gemm_wh_kernel<<<dim3(D_OUT / BN, N_NODES / BM), 256>>>(h, Ww, Wb);
    pack_whB_kernel<<<dim3(4, NCH), 256>>>();
    scores_kernel<<<N_NODES / 8, 256>>>(aw);
    flash_mma_kernel<<<N_NODES / MT, FTHREADS, SMEM_TOTAL>>>(adj, ab, out);
}

// round 5
// speedup vs baseline: 1.5197x; 1.5197x over previous
#include <cuda_runtime.h>
#include <cuda_fp16.h>
#include <cstdint>

#define N_NODES 8192
#define D_IN    512
#define D_OUT   256
#define KC      64
#define NCH     (N_NODES / KC)
#define MT      64
#define FTH     512

// ---------------- scratch (device globals) ----------------------------------
static __device__ float  g_wh [N_NODES * D_OUT];   // 8 MB
static __device__ __half g_whT[D_OUT * N_NODES];   // 4 MB fp16 wh^T
static __device__ float  g_ssrc[N_NODES];
static __device__ float  g_t[N_NODES];
static __device__ float  g_E[N_NODES];             // exp(t - T)
static __device__ float  g_F[N_NODES];             // exp(0.2(t - T))
static __device__ float  g_alpha[N_NODES];
static __device__ float  g_beta[N_NODES];
static __device__ float  g_thr[N_NODES];

// ---------------- PTX helpers -----------------------------------------------
__device__ __forceinline__ uint32_t smem_u32(const void* p) {
    uint32_t a;
    asm("{ .reg .u64 t; cvta.to.shared.u64 t, %1; cvt.u32.u64 %0, t; }"
        : "=r"(a) : "l"(p));
    return a;
}
__device__ __forceinline__ void ldmatrix_x4(uint32_t& r0, uint32_t& r1,
                                            uint32_t& r2, uint32_t& r3,
                                            uint32_t addr) {
    asm volatile("ldmatrix.sync.aligned.m8n8.x4.shared.b16 {%0,%1,%2,%3}, [%4];"
                 : "=r"(r0), "=r"(r1), "=r"(r2), "=r"(r3) : "r"(addr));
}
__device__ __forceinline__ void mma16816(float* c,
                                         uint32_t a0, uint32_t a1, uint32_t a2, uint32_t a3,
                                         uint32_t b0, uint32_t b1) {
    asm volatile("mma.sync.aligned.m16n8k16.row.col.f32.f16.f16.f32 "
                 "{%0,%1,%2,%3}, {%4,%5,%6,%7}, {%8,%9}, {%0,%1,%2,%3};"
                 : "+f"(c[0]), "+f"(c[1]), "+f"(c[2]), "+f"(c[3])
                 : "r"(a0), "r"(a1), "r"(a2), "r"(a3), "r"(b0), "r"(b1));
}
__device__ __forceinline__ void cp16(uint32_t dst, const void* src) {
    asm volatile("cp.async.ca.shared.global [%0], [%1], 16;"
                 :: "r"(dst), "l"(src) : "memory");
}
#define CP_COMMIT() asm volatile("cp.async.commit_group;" ::: "memory")
#define CP_WAIT0()  asm volatile("cp.async.wait_group 0;" ::: "memory")

// ==================== Kernel 1: wh = h @ W^T + b (fp32 SIMT) ================
#define BM 128
#define BN 128
#define BK 16
#define TM 8
#define TN 8

__global__ void __launch_bounds__(256) gemm_wh_kernel(
    const float* __restrict__ h, const float* __restrict__ W,
    const float* __restrict__ Wb)
{
    __shared__ float As[BK][BM + 4];
    __shared__ float Bs[BK][BN + 4];
    const int tid = threadIdx.x;
    const int tx = tid & 15;
    const int ty = tid >> 4;
    const int row0 = blockIdx.y * BM;
    const int col0 = blockIdx.x * BN;

    float acc[TM][TN];
    #pragma unroll
    for (int i = 0; i < TM; i++)
        #pragma unroll
        for (int j = 0; j < TN; j++) acc[i][j] = 0.f;

    for (int kb = 0; kb < D_IN; kb += BK) {
        #pragma unroll
        for (int l = 0; l < 2; l++) {
            int f = tid + l * 256;
            int r = f >> 2;
            int c = (f & 3) << 2;
            float4 v = *(const float4*)&h[(size_t)(row0 + r) * D_IN + kb + c];
            As[c + 0][r] = v.x; As[c + 1][r] = v.y;
            As[c + 2][r] = v.z; As[c + 3][r] = v.w;
            float4 u = *(const float4*)&W[(size_t)(col0 + r) * D_IN + kb + c];
            Bs[c + 0][r] = u.x; Bs[c + 1][r] = u.y;
            Bs[c + 2][r] = u.z; Bs[c + 3][r] = u.w;
        }
        __syncthreads();
        #pragma unroll
        for (int k = 0; k < BK; k++) {
            float a[TM], b[TN];
            #pragma unroll
            for (int i = 0; i < TM; i++) a[i] = As[k][ty * TM + i];
            #pragma unroll
            for (int j = 0; j < TN; j++) b[j] = Bs[k][tx * TN + j];
            #pragma unroll
            for (int i = 0; i < TM; i++)
                #pragma unroll
                for (int j = 0; j < TN; j++)
                    acc[i][j] += a[i] * b[j];
        }
        __syncthreads();
    }

    #pragma unroll
    for (int i = 0; i < TM; i++) {
        int gr = row0 + ty * TM + i;
        #pragma unroll
        for (int j = 0; j < TN; j += 4) {
            int gc = col0 + tx * TN + j;
            float4 v;
            v.x = acc[i][j + 0] + Wb[gc + 0];
            v.y = acc[i][j + 1] + Wb[gc + 1];
            v.z = acc[i][j + 2] + Wb[gc + 2];
            v.w = acc[i][j + 3] + Wb[gc + 3];
            *(float4*)&g_wh[(size_t)gr * D_OUT + gc] = v;
        }
    }
}

// ==================== Kernel 1b: whT fp16 = transpose(wh) ===================
__global__ void __launch_bounds__(256) transpose_wh_kernel()
{
    __shared__ __half tile[32][33];
    const int tx = threadIdx.x & 31;
    const int ty = threadIdx.x >> 5;
    const int c0 = blockIdx.x * 32;
    const int r0 = blockIdx.y * 32;
    #pragma unroll
    for (int i = 0; i < 4; i++) {
        int rr = ty + i * 8;
        tile[rr][tx] = __float2half(g_wh[(size_t)(r0 + rr) * D_OUT + c0 + tx]);
    }
    __syncthreads();
    #pragma unroll
    for (int i = 0; i < 4; i++) {
        int cc = ty + i * 8;
        g_whT[(size_t)(c0 + cc) * N_NODES + r0 + tx] = tile[tx][cc];
    }
}

// ==================== Kernel 2: per-row scores ==============================
__global__ void __launch_bounds__(256) scores_kernel(const float* __restrict__ aw)
{
    const int lane = threadIdx.x & 31;
    const int warp = threadIdx.x >> 5;
    const int row  = blockIdx.x * 8 + warp;

    const float4* whr = (const float4*)&g_wh[(size_t)row * D_OUT];
    float4 w0 = whr[lane * 2];
    float4 w1 = whr[lane * 2 + 1];
    const float4* as = (const float4*)aw;
    const float4* ad = (const float4*)(aw + D_OUT);
    float4 a0 = as[lane * 2], a1 = as[lane * 2 + 1];
    float4 b0 = ad[lane * 2], b1 = ad[lane * 2 + 1];

    float ss = w0.x*a0.x + w0.y*a0.y + w0.z*a0.z + w0.w*a0.w
             + w1.x*a1.x + w1.y*a1.y + w1.z*a1.z + w1.w*a1.w;
    float sd = w0.x*b0.x + w0.y*b0.y + w0.z*b0.z + w0.w*b0.w
             + w1.x*b1.x + w1.y*b1.y + w1.z*b1.z + w1.w*b1.w;
    #pragma unroll
    for (int o = 16; o; o >>= 1) {
        ss += __shfl_xor_sync(0xffffffffu, ss, o);
        sd += __shfl_xor_sync(0xffffffffu, sd, o);
    }
    if (lane == 0) {
        g_ssrc[row] = ss;
        g_t[row]    = sd;
    }
}

// ==================== Kernel 2b: finalize (T + per-node exps) ===============
__global__ void __launch_bounds__(1024) finalize_kernel(const float* __restrict__ abp)
{
    __shared__ float red[32];
    const int tid = threadIdx.x;
    float m = -3.0e38f;
    #pragma unroll
    for (int k = 0; k < 8; k++) m = fmaxf(m, g_t[tid + k * 1024]);
    #pragma unroll
    for (int o = 16; o; o >>= 1) m = fmaxf(m, __shfl_xor_sync(0xffffffffu, m, o));
    if ((tid & 31) == 0) red[tid >> 5] = m;
    __syncthreads();
    float T = red[0];
    #pragma unroll
    for (int w = 1; w < 32; w++) T = fmaxf(T, red[w]);

    const float ab = abp[0];
    #pragma unroll
    for (int k = 0; k < 8; k++) {
        int i = tid + k * 1024;
        float t = g_t[i];
        g_E[i] = __expf(t - T);
        g_F[i] = __expf(0.2f * (t - T));
        float u = g_ssrc[i] + ab + T;
        float M = u > 0.f ? u : 0.2f * u;
        g_alpha[i] = __expf(u - M);
        g_beta[i]  = __expf(0.2f * u - M);
        g_thr[i]   = __expf(-u);
    }
}

// ==================== Kernel 3: HMMA flash (cp.async pipelined) ==============
#define LD 72                                   // halves per smem row (144 B)
static constexpr uint32_t BS_BUF = 256 * LD * 2;          // 36864
static constexpr uint32_t AS_OFF = 2 * BS_BUF;            // 73728
static constexpr uint32_t AS_BUF = MT * LD * 2;           // 9216
static constexpr uint32_t ES_OFF = AS_OFF + 2 * AS_BUF;   // 92160
static constexpr uint32_t FS_OFF = ES_OFF + N_NODES * 4;  // 124928
static constexpr uint32_t LS_OFF = FS_OFF + N_NODES * 4;  // 157696
static constexpr uint32_t SMEM_TOTAL = LS_OFF + 256;      // 157952

__global__ void __launch_bounds__(FTH) flash_mma_kernel(
    const int* __restrict__ adj, float* __restrict__ out)
{
    extern __shared__ __align__(16) char smem[];
    const uint32_t sbase = smem_u32(smem);
    float* Es = (float*)(smem + ES_OFF);
    float* Fs = (float*)(smem + FS_OFF);
    float* lsum_s = (float*)(smem + LS_OFF);

    const int tid  = threadIdx.x;
    const int lane = tid & 31;
    const int warp = tid >> 5;
    const int rowbase = blockIdx.x * MT;

    // ---- prestage E,F (64 KB) ----
    #pragma unroll
    for (int i = 0; i < 4; i++) {
        int f = tid + i * FTH;
        ((float4*)Es)[f] = ((const float4*)g_E)[f];
        ((float4*)Fs)[f] = ((const float4*)g_F)[f];
    }

    // ---- per-thread P-gen constants ----
    const int prow = tid >> 3;           // 0..63
    const int pseg = tid & 7;            // 8 j's each
    const int row  = rowbase + prow;
    const float alpha = g_alpha[row];
    const float beta  = g_beta[row];
    const float thr   = g_thr[row];
    float lpriv = 0.f;

    const int* adjrow = adj + (size_t)row * N_NODES;
    const uint32_t a_st0 = sbase + AS_OFF + (uint32_t)((prow * LD + pseg * 8) * 2);

    // ---- mma addressing: warp grid 2m x 8n ----
    const int mw = warp >> 3;            // 0..1
    const int nw = warp & 7;             // 0..7
    const uint32_t a_lane0 = sbase + AS_OFF +
        (uint32_t)(((mw * 32 + (lane & 15)) * LD + (lane >> 4) * 8) * 2);
    const uint32_t b_lane0 = sbase +
        (uint32_t)(((nw * 32 + (lane & 7) + ((lane >> 4) << 3)) * LD
                    + ((lane >> 3) & 1) * 8) * 2);

    float acc[2][4][4];
    #pragma unroll
    for (int mi = 0; mi < 2; mi++)
        #pragma unroll
        for (int nt = 0; nt < 4; nt++)
            #pragma unroll
            for (int u = 0; u < 4; u++) acc[mi][nt][u] = 0.f;

    // ---- B stage via cp.async: 4 x 16B per thread ----
    auto stageB = [&](int kc, int buf) {
        const int k0 = kc * KC;
        const uint32_t bb = sbase + (uint32_t)buf * BS_BUF;
        #pragma unroll
        for (int i = 0; i < 4; i++) {
            int f = tid + i * FTH;       // 0..2047
            int n = f >> 3;
            int c = (f & 7) * 8;
            cp16(bb + (uint32_t)((n * LD + c) * 2),
                 g_whT + (size_t)n * N_NODES + k0 + c);
        }
    };

    // ---- P-gen: 8 weights into As[buf] ----
    auto pgen = [&](int kc, int buf) {
        const int k0 = kc * KC;
        const int jb = k0 + pseg * 8;
        int4 q0 = *(const int4*)(adjrow + jb);
        int4 q1 = *(const int4*)(adjrow + jb + 4);
        float4 e0 = *(const float4*)(Es + jb);
        float4 e1 = *(const float4*)(Es + jb + 4);
        float4 f0 = *(const float4*)(Fs + jb);
        float4 f1 = *(const float4*)(Fs + jb + 4);
        float p0 = q0.x > 0 ? (e0.x > thr ? alpha * e0.x : beta * f0.x) : 0.f;
        float p1 = q0.y > 0 ? (e0.y > thr ? alpha * e0.y : beta * f0.y) : 0.f;
        float p2 = q0.z > 0 ? (e0.z > thr ? alpha * e0.z : beta * f0.z) : 0.f;
        float p3 = q0.w > 0 ? (e0.w > thr ? alpha * e0.w : beta * f0.w) : 0.f;
        float p4 = q1.x > 0 ? (e1.x > thr ? alpha * e1.x : beta * f1.x) : 0.f;
        float p5 = q1.y > 0 ? (e1.y > thr ? alpha * e1.y : beta * f1.y) : 0.f;
        float p6 = q1.z > 0 ? (e1.z > thr ? alpha * e1.z : beta * f1.z) : 0.f;
        float p7 = q1.w > 0 ? (e1.w > thr ? alpha * e1.w : beta * f1.w) : 0.f;
        lpriv += ((p0 + p1) + (p2 + p3)) + ((p4 + p5) + (p6 + p7));
        __half2 h0 = __floats2half2_rn(p0, p1);
        __half2 h1 = __floats2half2_rn(p2, p3);
        __half2 h2 = __floats2half2_rn(p4, p5);
        __half2 h3 = __floats2half2_rn(p6, p7);
        uint4 w;
        w.x = *(uint32_t*)&h0; w.y = *(uint32_t*)&h1;
        w.z = *(uint32_t*)&h2; w.w = *(uint32_t*)&h3;
        uint32_t dst = a_st0 + (uint32_t)buf * AS_BUF;
        asm volatile("st.shared.v4.b32 [%0], {%1,%2,%3,%4};"
                     :: "r"(dst), "r"(w.x), "r"(w.y), "r"(w.z), "r"(w.w) : "memory");
    };

    // ---- prologue ----
    stageB(0, 0);
    CP_COMMIT();
    __syncthreads();          // Es/Fs visible
    pgen(0, 0);
    CP_WAIT0();
    __syncthreads();          // Bs[0], As[0] ready

    // ---- main loop: one sync per chunk ----
    #pragma unroll 2
    for (int kt = 0; kt < NCH; kt++) {
        const int buf = kt & 1;
        if (kt + 1 < NCH) { stageB(kt + 1, buf ^ 1); CP_COMMIT(); }

        const uint32_t a_lane = a_lane0 + (uint32_t)buf * AS_BUF;
        const uint32_t b_lane = b_lane0 + (uint32_t)buf * BS_BUF;
        #pragma unroll
        for (int ks = 0; ks < 4; ks++) {
            uint32_t b[2][4];
            ldmatrix_x4(b[0][0], b[0][1], b[0][2], b[0][3],
                        b_lane + (uint32_t)(ks * 32));
            ldmatrix_x4(b[1][0], b[1][1], b[1][2], b[1][3],
                        b_lane + (uint32_t)(16 * LD * 2 + ks * 32));
            #pragma unroll
            for (int mi = 0; mi < 2; mi++) {
                uint32_t a0, a1, a2, a3;
                ldmatrix_x4(a0, a1, a2, a3,
                            a_lane + (uint32_t)(mi * 16 * LD * 2 + ks * 32));
                mma16816(acc[mi][0], a0, a1, a2, a3, b[0][0], b[0][1]);
                mma16816(acc[mi][1], a0, a1, a2, a3, b[0][2], b[0][3]);
                mma16816(acc[mi][2], a0, a1, a2, a3, b[1][0], b[1][1]);
                mma16816(acc[mi][3], a0, a1, a2, a3, b[1][2], b[1][3]);
            }
        }
        if (kt + 1 < NCH) pgen(kt + 1, buf ^ 1);
        CP_WAIT0();
        __syncthreads();
    }

    // ---- lsum: reduce over 8 threads sharing a row ----
    lpriv += __shfl_xor_sync(0xffffffffu, lpriv, 1);
    lpriv += __shfl_xor_sync(0xffffffffu, lpriv, 2);
    lpriv += __shfl_xor_sync(0xffffffffu, lpriv, 4);
    if ((lane & 7) == 0) lsum_s[prow] = lpriv;
    __syncthreads();

    // ---- write out ----
    #pragma unroll
    for (int mi = 0; mi < 2; mi++) {
        int r0 = mw * 32 + mi * 16 + (lane >> 2);
        int r1 = r0 + 8;
        float inv0 = 1.f / lsum_s[r0];
        float inv1 = 1.f / lsum_s[r1];
        #pragma unroll
        for (int nt = 0; nt < 4; nt++) {
            int c = nw * 32 + nt * 8 + ((lane & 3) << 1);
            float2 v0 = make_float2(acc[mi][nt][0] * inv0, acc[mi][nt][1] * inv0);
            float2 v1 = make_float2(acc[mi][nt][2] * inv1, acc[mi][nt][3] * inv1);
            *(float2*)&out[(size_t)(rowbase + r0) * D_OUT + c] = v0;
            *(float2*)&out[(size_t)(rowbase + r1) * D_OUT + c] = v1;
        }
    }
}

// ==================== launch ================================================
extern "C" void kernel_launch(void* const* d_in, const int* in_sizes, int n_in,
                              void* d_out, int out_size)
{
    const float* h   = (const float*)d_in[0];
    const int*   adj = (const int*)  d_in[1];
    const float* Ww  = (const float*)d_in[2];
    const float* Wb  = (const float*)d_in[3];
    const float* aw  = (const float*)d_in[4];
    const float* ab  = (const float*)d_in[5];
    float* out = (float*)d_out;

    cudaFuncSetAttribute(flash_mma_kernel,
                         cudaFuncAttributeMaxDynamicSharedMemorySize, SMEM_TOTAL);

    gemm_wh_kernel<<<dim3(D_OUT / BN, N_NODES / BM), 256>>>(h, Ww, Wb);
    transpose_wh_kernel<<<dim3(D_OUT / 32, N_NODES / 32), 256>>>();
    scores_kernel<<<N_NODES / 8, 256>>>(aw);
    finalize_kernel<<<1, 1024>>>(ab);
    flash_mma_kernel<<<N_NODES / MT, FTH, SMEM_TOTAL>>>(adj, out);
}